// round 14
// baseline (speedup 1.0000x reference)
#include <cuda_runtime.h>
#include <cuda_bf16.h>
#include <cstdint>
#include <cstddef>

#define B_    32
#define T1_   512
#define T2_   2048
#define CENC  512
#define HCH   80
#define SLOPE_ 0.3f
#define TEMP_  0.0005f
#define NEGV  -1000000000.0f

__device__ float g_K [B_*HCH*T1_];        // final K fp32 (sumsq)
__device__ float g_QA[B_*HCH*T2_];        // final Q fp32 (sumsq)
__device__ float g_k2[B_*T1_];
__device__ float g_q2[B_*T2_];
__device__ float g_lpT[(size_t)B_*T2_*T1_];
__device__ uint32_t g_pkA [B_*HCH*T2_];   // packed bf16 hi/lo planes
__device__ uint32_t g_pkB [B_*HCH*T2_];
__device__ uint32_t g_pkK1[B_*HCH*T1_];
__device__ uint32_t g_pkK [B_*HCH*T1_];
__device__ __nv_bfloat16 g_WK1[24*2*HCH*72];
__device__ __nv_bfloat16 g_WK2[3*2*HCH*88];
__device__ __nv_bfloat16 g_WQ1[7*2*HCH*88];
__device__ __nv_bfloat16 g_WQ2[7*2*HCH*88];
__device__ __nv_bfloat16 g_WQ3[7*2*HCH*88];

// ---------------- helpers ----------------------------------------------------
__device__ __forceinline__ uint32_t smem_u32(const void* p) {
    uint32_t a;
    asm("{ .reg .u64 t; cvta.to.shared.u64 t, %1; cvt.u32.u64 %0, t; }" : "=r"(a) : "l"(p));
    return a;
}
__device__ __forceinline__ void ldmat4(uint32_t* r, uint32_t addr) {
    asm volatile("ldmatrix.sync.aligned.m8n8.x4.shared.b16 {%0,%1,%2,%3}, [%4];"
        : "=r"(r[0]), "=r"(r[1]), "=r"(r[2]), "=r"(r[3]) : "r"(addr));
}
__device__ __forceinline__ void ldmat2(uint32_t* r, uint32_t addr) {
    asm volatile("ldmatrix.sync.aligned.m8n8.x2.shared.b16 {%0,%1}, [%2];"
        : "=r"(r[0]), "=r"(r[1]) : "r"(addr));
}
__device__ __forceinline__ void mma16816(float* d, const uint32_t* a, const uint32_t* b) {
    asm volatile("mma.sync.aligned.m16n8k16.row.col.f32.bf16.bf16.f32 "
        "{%0,%1,%2,%3}, {%4,%5,%6,%7}, {%8,%9}, {%0,%1,%2,%3};"
        : "+f"(d[0]), "+f"(d[1]), "+f"(d[2]), "+f"(d[3])
        : "r"(a[0]), "r"(a[1]), "r"(a[2]), "r"(a[3]), "r"(b[0]), "r"(b[1]));
}
__device__ __forceinline__ void bf16split(float v, __nv_bfloat16& h, __nv_bfloat16& l) {
    h = __float2bfloat16(v);
    l = __float2bfloat16(v - __bfloat162float(h));
}
__device__ __forceinline__ uint32_t packhl(float v) {
    __nv_bfloat16 h, l;
    bf16split(v, h, l);
    return (uint32_t)__bfloat16_as_ushort(h) | ((uint32_t)__bfloat16_as_ushort(l) << 16);
}
__device__ __forceinline__ void cp_async16(uint32_t dst, const void* src) {
    asm volatile("cp.async.cg.shared.global [%0], [%1], 16;" :: "r"(dst), "l"(src));
}

// ---------------- weight prep: fp32 -> bf16 hi/lo planes ---------------------
__global__ void prep_w(const float* __restrict__ w, __nv_bfloat16* __restrict__ dst,
                       int CIN, int KSZ, int CB, int CVS)
{
    int idx = blockIdx.x * 256 + threadIdx.x;
    int NCB = CIN / CB;
    int total = NCB * KSZ * HCH * CB;
    if (idx >= total) return;
    int ci = idx % CB; int r = idx / CB;
    int oc = r % HCH; r /= HCH;
    int k  = r % KSZ; int cb = r / KSZ;
    float v = w[((size_t)oc*CIN + cb*CB + ci)*KSZ + k];
    __nv_bfloat16 h, l;
    bf16split(v, h, l);
    size_t base = (size_t)(cb*KSZ + k) * 2 * HCH * CVS;
    dst[base + (size_t)oc*CVS + ci] = h;
    dst[base + (size_t)HCH*CVS + (size_t)oc*CVS + ci] = l;
}

// =================== attn distance GEMM (packed input) ======================
#define AT_STRIDE 88
#define AT_TILE   (128*AT_STRIDE*2)
#define SM_AH 0
#define SM_AL (SM_AH + AT_TILE)
#define SM_BH (SM_AL + AT_TILE)
#define SM_BL (SM_BH + AT_TILE)
#define SM_Q2 (SM_BL + AT_TILE)
#define SM_K2 (SM_Q2 + 512)
#define ATTN_SMEM (SM_K2 + 512)
#define SM_OUT 0
#define OUT_STRIDE 132

__global__ void __launch_bounds__(256) attn_mma_kernel(
        const uint32_t* __restrict__ Qpk, const uint32_t* __restrict__ Kpk,
        const float* __restrict__ q2s, const float* __restrict__ k2s,
        float* __restrict__ outp)
{
    extern __shared__ char smem[];
    const uint32_t smb = smem_u32(smem);
    const int tid  = threadIdx.x;
    const int wid  = tid >> 5;
    const int lane = tid & 31;
    const int t2_0 = blockIdx.x * 128;
    const int t1_0 = blockIdx.y * 128;
    const int b    = blockIdx.z;

    for (int idx = tid; idx < HCH*128; idx += 256) {
        int c = idx >> 7, row = idx & 127;
        uint32_t w = Qpk[((size_t)b*HCH + c)*T2_ + t2_0 + row];
        *(uint16_t*)(smem + SM_AH + (row*AT_STRIDE + c)*2) = (uint16_t)(w & 0xffffu);
        *(uint16_t*)(smem + SM_AL + (row*AT_STRIDE + c)*2) = (uint16_t)(w >> 16);
    }
    for (int idx = tid; idx < HCH*128; idx += 256) {
        int c = idx >> 7, row = idx & 127;
        uint32_t w = Kpk[((size_t)b*HCH + c)*T1_ + t1_0 + row];
        *(uint16_t*)(smem + SM_BH + (row*AT_STRIDE + c)*2) = (uint16_t)(w & 0xffffu);
        *(uint16_t*)(smem + SM_BL + (row*AT_STRIDE + c)*2) = (uint16_t)(w >> 16);
    }
    if (tid < 128) {
        *(float*)(smem + SM_Q2 + tid*4) = q2s[(size_t)b*T2_ + t2_0 + tid];
        *(float*)(smem + SM_K2 + tid*4) = k2s[(size_t)b*T1_ + t1_0 + tid];
    }
    __syncthreads();

    const int m_blk = (wid & 1) * 64;
    const int n_blk = (wid >> 1) * 32;

    float acc[4][4][4];
#pragma unroll
    for (int mi = 0; mi < 4; mi++)
#pragma unroll
        for (int ni = 0; ni < 4; ni++)
#pragma unroll
            for (int q = 0; q < 4; q++) acc[mi][ni][q] = 0.f;

    const uint32_t a_lrow = (uint32_t)(lane & 15);
    const uint32_t a_lcol = (uint32_t)((lane >> 4) << 3);
    const uint32_t b_lrow = (uint32_t)(lane & 7);
    const uint32_t b_lcol = (uint32_t)(((lane >> 3) & 1) << 3);

#pragma unroll
    for (int ks = 0; ks < 5; ks++) {
        const uint32_t kc = ks * 16;
        uint32_t Ah[4][4], Al[4][4], Bh[4][2], Bl[4][2];
#pragma unroll
        for (int mi = 0; mi < 4; mi++) {
            uint32_t off = ((m_blk + mi*16 + a_lrow)*AT_STRIDE + kc + a_lcol)*2;
            ldmat4(Ah[mi], smb + SM_AH + off);
            ldmat4(Al[mi], smb + SM_AL + off);
        }
#pragma unroll
        for (int ni = 0; ni < 4; ni++) {
            uint32_t off = ((n_blk + ni*8 + b_lrow)*AT_STRIDE + kc + b_lcol)*2;
            ldmat2(Bh[ni], smb + SM_BH + off);
            ldmat2(Bl[ni], smb + SM_BL + off);
        }
#pragma unroll
        for (int mi = 0; mi < 4; mi++)
#pragma unroll
            for (int ni = 0; ni < 4; ni++) {
                mma16816(acc[mi][ni], Ah[mi], Bh[ni]);
                mma16816(acc[mi][ni], Ah[mi], Bl[ni]);
                mma16816(acc[mi][ni], Al[mi], Bh[ni]);
            }
    }
    __syncthreads();

    const int gid = lane >> 2, tig = lane & 3;
    const float* sQ2 = (const float*)(smem + SM_Q2);
    const float* sK2 = (const float*)(smem + SM_K2);
#pragma unroll
    for (int mi = 0; mi < 4; mi++) {
        int r0 = m_blk + mi*16 + gid;
        int r1 = r0 + 8;
        float q20 = sQ2[r0], q21 = sQ2[r1];
#pragma unroll
        for (int ni = 0; ni < 4; ni++) {
            int c0 = n_blk + ni*8 + tig*2;
            float k20 = sK2[c0], k21 = sK2[c0 + 1];
            float2 lo, hi;
            lo.x = TEMP_*(2.f*acc[mi][ni][0] - q20 - k20);
            lo.y = TEMP_*(2.f*acc[mi][ni][1] - q20 - k21);
            hi.x = TEMP_*(2.f*acc[mi][ni][2] - q21 - k20);
            hi.y = TEMP_*(2.f*acc[mi][ni][3] - q21 - k21);
            *(float2*)(smem + SM_OUT + (r0*OUT_STRIDE + c0)*4) = lo;
            *(float2*)(smem + SM_OUT + (r1*OUT_STRIDE + c0)*4) = hi;
        }
    }
    __syncthreads();
#pragma unroll 4
    for (int it = 0; it < 16; it++) {
        int row = it*8 + (tid >> 5);
        float4 v = *(const float4*)(smem + SM_OUT + (row*OUT_STRIDE + lane*4)*4);
        *(float4*)&outp[((size_t)b*T2_ + t2_0 + row)*T1_ + t1_0 + lane*4] = v;
    }
}

// ====== conv: pre-split W via cp.async, packed X planes, TT=128, 2 CTAs/SM ===
template<int KSZ, int CIN>
struct CC3 {
    static constexpr int CB  = (CIN == 80) ? 80 : 64;
    static constexpr int NCB = CIN / CB;
    static constexpr int CVS = CB + 8;
    static constexpr int XR  = 128 + KSZ - 1;
    static constexpr int NKS = CB / 16;
    static constexpr int NJ  = NCB * KSZ;
    static constexpr int XHALF = XR * CVS * 2;
    static constexpr int WTAP  = 2 * HCH * CVS * 2;     // hi+lo planes, bytes
    static constexpr int O_XH = 0;
    static constexpr int O_XL = XHALF;
    static constexpr int O_W0 = 2*XHALF;
    static constexpr int O_W1 = O_W0 + WTAP;
    static constexpr int O_BIAS = O_W1 + WTAP;
    static constexpr int SMEM = O_BIAS + 512;
};
#define CV_TSTR 132

template<int KSZ, int PAD, int TLEN, int CIN, bool XPACKED, bool WF32>
__global__ void __launch_bounds__(256, 2) conv_mma3(
        const void* __restrict__ xin, const __nv_bfloat16* __restrict__ wbf,
        const float* __restrict__ bias, float* __restrict__ yf,
        uint32_t* __restrict__ ypk)
{
    using C = CC3<KSZ, CIN>;
    extern __shared__ char smem[];
    const uint32_t smb = smem_u32(smem);
    const int tid  = threadIdx.x;
    const int wid  = tid >> 5;
    const int lane = tid & 31;
    const int t0   = blockIdx.x * 128;
    const int b    = blockIdx.y;

    if (tid < HCH) *(float*)(smem + C::O_BIAS + tid*4) = bias[tid];

    // prime: tap 0 -> buf 0
    {
        constexpr int CNT = C::WTAP / 16;
        for (int i = tid; i < CNT; i += 256)
            cp_async16(smb + C::O_W0 + i*16, (const char*)wbf + i*16);
        asm volatile("cp.async.commit_group;");
    }

    const int m_blk = (wid >> 1) * 32;
    const int n_blk = (wid & 1) * 40;

    float acc[2][5][4];
#pragma unroll
    for (int mi = 0; mi < 2; mi++)
#pragma unroll
        for (int ni = 0; ni < 5; ni++)
#pragma unroll
            for (int q = 0; q < 4; q++) acc[mi][ni][q] = 0.f;

    const uint32_t a_lrow = (uint32_t)(lane & 15);
    const uint32_t a_lcol = (uint32_t)((lane >> 4) << 3);
    const uint32_t b_lrow = (uint32_t)(lane & 7);
    const uint32_t b_lcol = (uint32_t)(((lane >> 3) & 1) << 3);

#pragma unroll 1
    for (int j = 0; j < C::NJ; j++) {
        const int cb = j / KSZ, k = j - cb*KSZ;
        __syncthreads();  // syncA: all prev-tap mma done (protects W target buf + X region)
        if (k == 0) {
            for (int idx = tid; idx < C::CB*C::XR; idx += 256) {
                int c = idx / C::XR, r = idx - c*C::XR;
                int t = t0 + r - PAD;
                bool inr = ((unsigned)t < (unsigned)TLEN);
                if (XPACKED) {
                    const uint32_t* xp = (const uint32_t*)xin;
                    uint32_t w = inr ? xp[((size_t)b*CIN + cb*C::CB + c)*TLEN + t] : 0u;
                    *(uint16_t*)(smem + C::O_XH + (r*C::CVS + c)*2) = (uint16_t)(w & 0xffffu);
                    *(uint16_t*)(smem + C::O_XL + (r*C::CVS + c)*2) = (uint16_t)(w >> 16);
                } else {
                    const float* xf = (const float*)xin;
                    float v = inr ? xf[((size_t)b*CIN + cb*C::CB + c)*TLEN + t] : 0.f;
                    __nv_bfloat16 h, l;
                    bf16split(v, h, l);
                    *(__nv_bfloat16*)(smem + C::O_XH + (r*C::CVS + c)*2) = h;
                    *(__nv_bfloat16*)(smem + C::O_XL + (r*C::CVS + c)*2) = l;
                }
            }
        }
        if (j + 1 < C::NJ) {
            constexpr int CNT = C::WTAP / 16;
            uint32_t dst = smb + (((j+1) & 1) ? C::O_W1 : C::O_W0);
            const char* src = (const char*)wbf + (size_t)(j+1)*C::WTAP;
            for (int i = tid; i < CNT; i += 256)
                cp_async16(dst + i*16, src + i*16);
            asm volatile("cp.async.commit_group;");
            asm volatile("cp.async.wait_group 1;");
        } else {
            asm volatile("cp.async.wait_group 0;");
        }
        __syncthreads();  // syncB: W buf[j&1] + X visible

        const uint32_t wb = smb + ((j & 1) ? C::O_W1 : C::O_W0);
#pragma unroll
        for (int ks = 0; ks < C::NKS; ks++) {
            const uint32_t kc = ks * 16;
            uint32_t Ah[2][4], Al[2][4], Bh[5][2], Bl[5][2];
#pragma unroll
            for (int mi = 0; mi < 2; mi++) {
                uint32_t off = ((uint32_t)(m_blk + mi*16 + k + a_lrow)*C::CVS + kc + a_lcol)*2;
                ldmat4(Ah[mi], smb + C::O_XH + off);
                ldmat4(Al[mi], smb + C::O_XL + off);
            }
#pragma unroll
            for (int ni = 0; ni < 5; ni++) {
                uint32_t off = ((uint32_t)(n_blk + ni*8 + b_lrow)*C::CVS + kc + b_lcol)*2;
                ldmat2(Bh[ni], wb + off);
                ldmat2(Bl[ni], wb + HCH*C::CVS*2 + off);
            }
#pragma unroll
            for (int mi = 0; mi < 2; mi++)
#pragma unroll
                for (int ni = 0; ni < 5; ni++) {
                    mma16816(acc[mi][ni], Ah[mi], Bh[ni]);
                    mma16816(acc[mi][ni], Ah[mi], Bl[ni]);
                    mma16816(acc[mi][ni], Al[mi], Bh[ni]);
                }
        }
    }
    __syncthreads();   // done with X/W smem; bounce tile reuses it

    const int gid = lane >> 2, tig = lane & 3;
    const float* sB = (const float*)(smem + C::O_BIAS);
#pragma unroll
    for (int mi = 0; mi < 2; mi++) {
        int r0 = m_blk + mi*16 + gid;
        int r1 = r0 + 8;
#pragma unroll
        for (int ni = 0; ni < 5; ni++) {
            int c0 = n_blk + ni*8 + tig*2;
            float b0 = sB[c0], b1 = sB[c0+1];
            float v;
            v = acc[mi][ni][0] + b0; v = v >= 0.f ? v : SLOPE_*v;
            *(float*)(smem + (c0*CV_TSTR + r0)*4) = v;
            v = acc[mi][ni][1] + b1; v = v >= 0.f ? v : SLOPE_*v;
            *(float*)(smem + ((c0+1)*CV_TSTR + r0)*4) = v;
            v = acc[mi][ni][2] + b0; v = v >= 0.f ? v : SLOPE_*v;
            *(float*)(smem + (c0*CV_TSTR + r1)*4) = v;
            v = acc[mi][ni][3] + b1; v = v >= 0.f ? v : SLOPE_*v;
            *(float*)(smem + ((c0+1)*CV_TSTR + r1)*4) = v;
        }
    }
    __syncthreads();
    for (int idx = tid; idx < HCH*32; idx += 256) {
        int oc = idx >> 5, t4 = idx & 31;
        float4 v = *(const float4*)(smem + (oc*CV_TSTR + t4*4)*4);
        size_t o = ((size_t)b*HCH + oc)*TLEN + t0 + t4*4;
        if (WF32) *(float4*)&yf[o] = v;
        uint4 pk;
        pk.x = packhl(v.x); pk.y = packhl(v.y);
        pk.z = packhl(v.z); pk.w = packhl(v.w);
        *(uint4*)&ypk[o] = pk;
    }
}

// ---------------------------------------------------------------------------
__global__ void __launch_bounds__(256) transpose_logprior(
        const float* __restrict__ prior, float* __restrict__ lpT)
{
    __shared__ float tile[32][33];
    const int b = blockIdx.z;
    const int t1_0 = blockIdx.x * 32, t2_0 = blockIdx.y * 32;
    const int tx = threadIdx.x, ty = threadIdx.y;
#pragma unroll
    for (int i = 0; i < 4; i++)
        tile[ty + 8*i][tx] = prior[((size_t)b*T1_ + t1_0 + ty + 8*i)*T2_ + t2_0 + tx];
    __syncthreads();
#pragma unroll
    for (int i = 0; i < 4; i++)
        lpT[((size_t)b*T2_ + t2_0 + ty + 8*i)*T1_ + t1_0 + tx] =
            logf(tile[tx][ty + 8*i] + 1e-8f);
}

template<int C, int T>
__global__ void __launch_bounds__(256) sumsq_kernel(
        const float* __restrict__ x, float* __restrict__ out)
{
    int idx = blockIdx.x * 256 + threadIdx.x;
    int b = idx / T, t = idx - b*T;
    float s = 0.f;
#pragma unroll 8
    for (int c = 0; c < C; c++) {
        float v = x[((size_t)b*C + c)*T + t];
        s = fmaf(v, v, s);
    }
    out[idx] = s;
}

__device__ __forceinline__ float blkMax(float v, float* sh) {
#pragma unroll
    for (int o = 16; o; o >>= 1) v = fmaxf(v, __shfl_xor_sync(0xffffffffu, v, o));
    if ((threadIdx.x & 31) == 0) sh[threadIdx.x >> 5] = v;
    __syncthreads();
    float r = sh[0];
#pragma unroll
    for (int i = 1; i < 8; i++) r = fmaxf(r, sh[i]);
    __syncthreads();
    return r;
}
__device__ __forceinline__ float blkSum(float v, float* sh) {
#pragma unroll
    for (int o = 16; o; o >>= 1) v += __shfl_xor_sync(0xffffffffu, v, o);
    if ((threadIdx.x & 31) == 0) sh[threadIdx.x >> 5] = v;
    __syncthreads();
    float r = sh[0];
#pragma unroll
    for (int i = 1; i < 8; i++) r += sh[i];
    __syncthreads();
    return r;
}

__global__ void __launch_bounds__(256) rowsoft_kernel(
        float* __restrict__ lp, float* __restrict__ lpT,
        float* __restrict__ soft)
{
    __shared__ float sh[8];
    const size_t off = (size_t)blockIdx.x * T1_;
    const int tid = threadIdx.x;
    float v0 = lp[off + tid], v1 = lp[off + 256 + tid];
    float m  = blkMax(fmaxf(v0, v1), sh);
    float s  = blkSum(__expf(v0 - m) + __expf(v1 - m), sh);
    float lse = m + __logf(s);
    float a0 = v0 - lse + lpT[off + tid];
    float a1 = v1 - lse + lpT[off + 256 + tid];
    float m2 = blkMax(fmaxf(a0, a1), sh);
    float p0 = expf(a0 - m2), p1 = expf(a1 - m2);
    float s2 = blkSum(p0 + p1, sh);
    float inv = 1.0f / s2;
    float ls2 = logf(s2);
    lp[off + tid] = a0;                lp[off + 256 + tid] = a1;
    soft[off + tid] = p0 * inv;        soft[off + 256 + tid] = p1 * inv;
    lpT[off + tid] = a0 - m2 - ls2;    lpT[off + 256 + tid] = a1 - m2 - ls2;
}

__global__ void zero_kernel(float4* __restrict__ p) {
    size_t i = (size_t)blockIdx.x * blockDim.x + threadIdx.x;
    p[i] = make_float4(0.f, 0.f, 0.f, 0.f);
}

#define MAS_RING 8
#define MAS_SMEM (T2_*32*2 + T1_*4)

__global__ void __launch_bounds__(32) mas_kernel(
        const float* __restrict__ la, const int* __restrict__ enc_len,
        const int* __restrict__ dec_len, float* __restrict__ hard,
        float* __restrict__ dur)
{
    extern __shared__ unsigned short sBits[];
    int* durS = (int*)&sBits[T2_*32];
    const int b = blockIdx.x;
    const int lane = threadIdx.x;
    const int el = enc_len[b];
    const int dl = dec_len[b];
    const float* rowbase = la + (size_t)b*T2_*T1_ + lane*16;

    unsigned validbits = 0u;
    float logp[16];
#pragma unroll
    for (int k = 0; k < 16; k++) {
        logp[k] = (lane == 0 && k == 0) ? 0.f : NEGV;
        if (lane*16 + k < el) validbits |= (1u << k);
    }
    float4 ring[MAS_RING][4];
#pragma unroll
    for (int p = 0; p < MAS_RING; p++)
#pragma unroll
        for (int q = 0; q < 4; q++)
            ring[p][q] = *(const float4*)(rowbase + (size_t)p*T1_ + q*4);

    for (int t2b = 0; t2b < T2_; t2b += MAS_RING) {
#pragma unroll
        for (int u = 0; u < MAS_RING; u++) {
            const int t2 = t2b + u;
            float rv[16];
            rv[0]=ring[u][0].x;  rv[1]=ring[u][0].y;  rv[2]=ring[u][0].z;  rv[3]=ring[u][0].w;
            rv[4]=ring[u][1].x;  rv[5]=ring[u][1].y;  rv[6]=ring[u][1].z;  rv[7]=ring[u][1].w;
            rv[8]=ring[u][2].x;  rv[9]=ring[u][2].y;  rv[10]=ring[u][2].z; rv[11]=ring[u][2].w;
            rv[12]=ring[u][3].x; rv[13]=ring[u][3].y; rv[14]=ring[u][3].z; rv[15]=ring[u][3].w;
            const int tn = t2 + MAS_RING;
            if (tn < T2_) {
#pragma unroll
                for (int q = 0; q < 4; q++)
                    ring[u][q] = *(const float4*)(rowbase + (size_t)tn*T1_ + q*4);
            }
#pragma unroll
            for (int k = 0; k < 16; k++)
                rv[k] = ((validbits >> k) & 1u) ? rv[k] : NEGV;
            if (t2 == 0) {
#pragma unroll
                for (int k = 0; k < 16; k++)
                    if (lane > 0 || k > 0) rv[k] = NEGV;
            }
            float last = __shfl_up_sync(0xffffffffu, logp[15], 1);
            unsigned bits = 0u;
#pragma unroll
            for (int k = 15; k >= 0; k--) {
                float sh = (k == 0) ? last : logp[k-1];
                bool t1pos = (k > 0) || (lane > 0);
                bool take = t1pos && (sh >= logp[k]);
                float base = take ? sh : logp[k];
                if (take) bits |= (1u << k);
                logp[k] = rv[k] + base;
            }
            sBits[t2*32 + lane] = (unsigned short)bits;
        }
    }
    __syncwarp();
    for (int i = lane; i < T1_; i += 32) durS[i] = 0;
    __syncwarp();
    if (lane == 0) {
        int curr = el - 1;
        for (int i = T2_-1; i >= 0; --i) {
            if (i < dl) {
                hard[((size_t)b*T2_ + i)*T1_ + curr] = 1.0f;
                durS[curr]++;
                unsigned bits = sBits[i*32 + (curr >> 4)];
                curr -= (int)((bits >> (curr & 15)) & 1u);
            }
        }
    }
    __syncwarp();
    for (int i = lane; i < T1_; i += 32) dur[(size_t)b*T1_ + i] = (float)durS[i];
}

extern "C" void kernel_launch(void* const* d_in, const int* in_sizes, int n_in,
                              void* d_out, int out_size)
{
    const float* enc_in  = (const float*)d_in[0];
    const float* dec_in  = (const float*)d_in[1];
    const int*   enc_len = (const int*)d_in[2];
    const int*   dec_len = (const int*)d_in[3];
    const float* prior   = (const float*)d_in[5];
    const float* kw1 = (const float*)d_in[6];
    const float* kb1 = (const float*)d_in[7];
    const float* kw2 = (const float*)d_in[8];
    const float* kb2 = (const float*)d_in[9];
    const float* qw1 = (const float*)d_in[10];
    const float* qb1 = (const float*)d_in[11];
    const float* qw2 = (const float*)d_in[12];
    const float* qb2 = (const float*)d_in[13];
    const float* qw3 = (const float*)d_in[14];
    const float* qb3 = (const float*)d_in[15];

    float* outp = (float*)d_out;
    const size_t VOL = (size_t)B_*T2_*T1_;
    float* lp   = outp;
    float* soft = outp + VOL;
    float* hard = outp + 2*VOL;
    float* dur  = outp + 3*VOL;

    float *pK, *pQA, *pk2, *pq2, *plpT;
    uint32_t *ppkA, *ppkB, *ppkK1, *ppkK;
    __nv_bfloat16 *pWK1, *pWK2, *pWQ1, *pWQ2, *pWQ3;
    cudaGetSymbolAddress((void**)&pK,   g_K);
    cudaGetSymbolAddress((void**)&pQA,  g_QA);
    cudaGetSymbolAddress((void**)&pk2,  g_k2);
    cudaGetSymbolAddress((void**)&pq2,  g_q2);
    cudaGetSymbolAddress((void**)&plpT, g_lpT);
    cudaGetSymbolAddress((void**)&ppkA,  g_pkA);
    cudaGetSymbolAddress((void**)&ppkB,  g_pkB);
    cudaGetSymbolAddress((void**)&ppkK1, g_pkK1);
    cudaGetSymbolAddress((void**)&ppkK,  g_pkK);
    cudaGetSymbolAddress((void**)&pWK1, g_WK1);
    cudaGetSymbolAddress((void**)&pWK2, g_WK2);
    cudaGetSymbolAddress((void**)&pWQ1, g_WQ1);
    cudaGetSymbolAddress((void**)&pWQ2, g_WQ2);
    cudaGetSymbolAddress((void**)&pWQ3, g_WQ3);

    static int attrs_set = 0;
    if (!attrs_set) {
        cudaFuncSetAttribute(mas_kernel, cudaFuncAttributeMaxDynamicSharedMemorySize, MAS_SMEM);
        cudaFuncSetAttribute(attn_mma_kernel, cudaFuncAttributeMaxDynamicSharedMemorySize, ATTN_SMEM);
        cudaFuncSetAttribute(conv_mma3<7,3,T2_,HCH,false,false>,
            cudaFuncAttributeMaxDynamicSharedMemorySize, CC3<7,HCH>::SMEM);
        cudaFuncSetAttribute(conv_mma3<7,3,T2_,HCH,true,false>,
            cudaFuncAttributeMaxDynamicSharedMemorySize, CC3<7,HCH>::SMEM);
        cudaFuncSetAttribute(conv_mma3<7,3,T2_,HCH,true,true>,
            cudaFuncAttributeMaxDynamicSharedMemorySize, CC3<7,HCH>::SMEM);
        cudaFuncSetAttribute(conv_mma3<3,1,T1_,CENC,false,false>,
            cudaFuncAttributeMaxDynamicSharedMemorySize, CC3<3,CENC>::SMEM);
        cudaFuncSetAttribute(conv_mma3<3,1,T1_,HCH,true,true>,
            cudaFuncAttributeMaxDynamicSharedMemorySize, CC3<3,HCH>::SMEM);
        attrs_set = 1;
    }

    // weight prep (tiny)
    prep_w<<<(8*3*HCH*64 + 255)/256, 256>>>(kw1, pWK1, CENC, 3, 64, 72);
    prep_w<<<(3*HCH*HCH + 255)/256, 256>>>(kw2, pWK2, HCH, 3, 80, 88);
    prep_w<<<(7*HCH*HCH + 255)/256, 256>>>(qw1, pWQ1, HCH, 7, 80, 88);
    prep_w<<<(7*HCH*HCH + 255)/256, 256>>>(qw2, pWQ2, HCH, 7, 80, 88);
    prep_w<<<(7*HCH*HCH + 255)/256, 256>>>(qw3, pWQ3, HCH, 7, 80, 88);

    transpose_logprior<<<dim3(T1_/32, T2_/32, B_), dim3(32, 8)>>>(prior, plpT);

    conv_mma3<3,1,T1_,CENC,false,false><<<dim3(T1_/128, B_), 256, CC3<3,CENC>::SMEM>>>(
        enc_in, pWK1, kb1, nullptr, ppkK1);
    conv_mma3<3,1,T1_,HCH,true,true><<<dim3(T1_/128, B_), 256, CC3<3,HCH>::SMEM>>>(
        ppkK1, pWK2, kb2, pK, ppkK);
    conv_mma3<7,3,T2_,HCH,false,false><<<dim3(T2_/128, B_), 256, CC3<7,HCH>::SMEM>>>(
        dec_in, pWQ1, qb1, nullptr, ppkA);
    conv_mma3<7,3,T2_,HCH,true,false><<<dim3(T2_/128, B_), 256, CC3<7,HCH>::SMEM>>>(
        ppkA, pWQ2, qb2, nullptr, ppkB);
    conv_mma3<7,3,T2_,HCH,true,true><<<dim3(T2_/128, B_), 256, CC3<7,HCH>::SMEM>>>(
        ppkB, pWQ3, qb3, pQA, ppkA);

    sumsq_kernel<HCH, T1_><<<B_*T1_/256, 256>>>(pK,  pk2);
    sumsq_kernel<HCH, T2_><<<B_*T2_/256, 256>>>(pQA, pq2);

    attn_mma_kernel<<<dim3(T2_/128, T1_/128, B_), 256, ATTN_SMEM>>>(ppkA, ppkK, pq2, pk2, lp);
    rowsoft_kernel<<<B_*T2_, 256>>>(lp, plpT, soft);

    zero_kernel<<<(unsigned)(VOL/4/256), 256>>>((float4*)hard);

    mas_kernel<<<B_, 32, MAS_SMEM>>>(plpT, enc_len, dec_len, hard, dur);
}

// round 15
// speedup vs baseline: 1.3991x; 1.3991x over previous
#include <cuda_runtime.h>
#include <cuda_bf16.h>
#include <cstdint>
#include <cstddef>

#define B_    32
#define T1_   512
#define T2_   2048
#define CENC  512
#define HCH   80
#define SLOPE_ 0.3f
#define TEMP_  0.0005f
#define NEGV  -1000000000.0f

__device__ float g_K [B_*HCH*T1_];
__device__ float g_QA[B_*HCH*T2_];
__device__ float g_k2[B_*T1_];
__device__ float g_q2[B_*T2_];
__device__ float g_lpT[(size_t)B_*T2_*T1_];
__device__ uint32_t g_pkA [B_*HCH*T2_];
__device__ uint32_t g_pkB [B_*HCH*T2_];
__device__ uint32_t g_pkK1[B_*HCH*T1_];
__device__ uint32_t g_pkK [B_*HCH*T1_];
__device__ __nv_bfloat16 g_WK1[24*2*HCH*72];
__device__ __nv_bfloat16 g_WK2[3*2*HCH*88];
__device__ __nv_bfloat16 g_WQ1[7*2*HCH*88];
__device__ __nv_bfloat16 g_WQ2[7*2*HCH*88];
__device__ __nv_bfloat16 g_WQ3[7*2*HCH*88];

// ---------------- helpers ----------------------------------------------------
__device__ __forceinline__ uint32_t smem_u32(const void* p) {
    uint32_t a;
    asm("{ .reg .u64 t; cvta.to.shared.u64 t, %1; cvt.u32.u64 %0, t; }" : "=r"(a) : "l"(p));
    return a;
}
__device__ __forceinline__ void ldmat4(uint32_t* r, uint32_t addr) {
    asm volatile("ldmatrix.sync.aligned.m8n8.x4.shared.b16 {%0,%1,%2,%3}, [%4];"
        : "=r"(r[0]), "=r"(r[1]), "=r"(r[2]), "=r"(r[3]) : "r"(addr));
}
__device__ __forceinline__ void ldmat2(uint32_t* r, uint32_t addr) {
    asm volatile("ldmatrix.sync.aligned.m8n8.x2.shared.b16 {%0,%1}, [%2];"
        : "=r"(r[0]), "=r"(r[1]) : "r"(addr));
}
__device__ __forceinline__ void mma16816(float* d, const uint32_t* a, const uint32_t* b) {
    asm volatile("mma.sync.aligned.m16n8k16.row.col.f32.bf16.bf16.f32 "
        "{%0,%1,%2,%3}, {%4,%5,%6,%7}, {%8,%9}, {%0,%1,%2,%3};"
        : "+f"(d[0]), "+f"(d[1]), "+f"(d[2]), "+f"(d[3])
        : "r"(a[0]), "r"(a[1]), "r"(a[2]), "r"(a[3]), "r"(b[0]), "r"(b[1]));
}
__device__ __forceinline__ void bf16split(float v, __nv_bfloat16& h, __nv_bfloat16& l) {
    h = __float2bfloat16(v);
    l = __float2bfloat16(v - __bfloat162float(h));
}
__device__ __forceinline__ uint32_t packhl(float v) {
    __nv_bfloat16 h, l;
    bf16split(v, h, l);
    return (uint32_t)__bfloat16_as_ushort(h) | ((uint32_t)__bfloat16_as_ushort(l) << 16);
}
__device__ __forceinline__ void cp_async16(uint32_t dst, const void* src) {
    asm volatile("cp.async.cg.shared.global [%0], [%1], 16;" :: "r"(dst), "l"(src));
}

// ---------------- one-shot weight prep: all 5 tensors ------------------------
__device__ __forceinline__ void prep_one(const float* w, __nv_bfloat16* dst,
                                         int CIN, int KSZ, int CB, int CVS, int idx)
{
    int ci = idx % CB; int r = idx / CB;
    int oc = r % HCH; r /= HCH;
    int k  = r % KSZ; int cb = r / KSZ;
    float v = w[((size_t)oc*CIN + cb*CB + ci)*KSZ + k];
    __nv_bfloat16 h, l;
    bf16split(v, h, l);
    size_t base = (size_t)(cb*KSZ + k) * 2 * HCH * CVS;
    dst[base + (size_t)oc*CVS + ci] = h;
    dst[base + (size_t)HCH*CVS + (size_t)oc*CVS + ci] = l;
}
__global__ void prep_all(const float* kw1, const float* kw2, const float* qw1,
                         const float* qw2, const float* qw3,
                         __nv_bfloat16* dK1, __nv_bfloat16* dK2, __nv_bfloat16* dQ1,
                         __nv_bfloat16* dQ2, __nv_bfloat16* dQ3)
{
    int idx = blockIdx.x * 256 + threadIdx.x;
    const int s0 = 24*HCH*64;              // kw1: NCB=8,KSZ=3
    const int s1 = s0 + 3*HCH*HCH;
    const int s2 = s1 + 7*HCH*HCH;
    const int s3 = s2 + 7*HCH*HCH;
    const int s4 = s3 + 7*HCH*HCH;
    if (idx < s0)      prep_one(kw1, dK1, CENC, 3, 64, 72, idx);
    else if (idx < s1) prep_one(kw2, dK2, HCH, 3, 80, 88, idx - s0);
    else if (idx < s2) prep_one(qw1, dQ1, HCH, 7, 80, 88, idx - s1);
    else if (idx < s3) prep_one(qw2, dQ2, HCH, 7, 80, 88, idx - s2);
    else if (idx < s4) prep_one(qw3, dQ3, HCH, 7, 80, 88, idx - s3);
}

// =================== attn distance GEMM (packed input) ======================
#define AT_STRIDE 88
#define AT_TILE   (128*AT_STRIDE*2)
#define SM_AH 0
#define SM_AL (SM_AH + AT_TILE)
#define SM_BH (SM_AL + AT_TILE)
#define SM_BL (SM_BH + AT_TILE)
#define SM_Q2 (SM_BL + AT_TILE)
#define SM_K2 (SM_Q2 + 512)
#define ATTN_SMEM (SM_K2 + 512)
#define SM_OUT 0
#define OUT_STRIDE 132

__global__ void __launch_bounds__(256) attn_mma_kernel(
        const uint32_t* __restrict__ Qpk, const uint32_t* __restrict__ Kpk,
        const float* __restrict__ q2s, const float* __restrict__ k2s,
        float* __restrict__ outp)
{
    extern __shared__ char smem[];
    const uint32_t smb = smem_u32(smem);
    const int tid  = threadIdx.x;
    const int wid  = tid >> 5;
    const int lane = tid & 31;
    const int t2_0 = blockIdx.x * 128;
    const int t1_0 = blockIdx.y * 128;
    const int b    = blockIdx.z;

    for (int idx = tid; idx < HCH*128; idx += 256) {
        int c = idx >> 7, row = idx & 127;
        uint32_t w = Qpk[((size_t)b*HCH + c)*T2_ + t2_0 + row];
        *(uint16_t*)(smem + SM_AH + (row*AT_STRIDE + c)*2) = (uint16_t)(w & 0xffffu);
        *(uint16_t*)(smem + SM_AL + (row*AT_STRIDE + c)*2) = (uint16_t)(w >> 16);
    }
    for (int idx = tid; idx < HCH*128; idx += 256) {
        int c = idx >> 7, row = idx & 127;
        uint32_t w = Kpk[((size_t)b*HCH + c)*T1_ + t1_0 + row];
        *(uint16_t*)(smem + SM_BH + (row*AT_STRIDE + c)*2) = (uint16_t)(w & 0xffffu);
        *(uint16_t*)(smem + SM_BL + (row*AT_STRIDE + c)*2) = (uint16_t)(w >> 16);
    }
    if (tid < 128) {
        *(float*)(smem + SM_Q2 + tid*4) = q2s[(size_t)b*T2_ + t2_0 + tid];
        *(float*)(smem + SM_K2 + tid*4) = k2s[(size_t)b*T1_ + t1_0 + tid];
    }
    __syncthreads();

    const int m_blk = (wid & 1) * 64;
    const int n_blk = (wid >> 1) * 32;

    float acc[4][4][4];
#pragma unroll
    for (int mi = 0; mi < 4; mi++)
#pragma unroll
        for (int ni = 0; ni < 4; ni++)
#pragma unroll
            for (int q = 0; q < 4; q++) acc[mi][ni][q] = 0.f;

    const uint32_t a_lrow = (uint32_t)(lane & 15);
    const uint32_t a_lcol = (uint32_t)((lane >> 4) << 3);
    const uint32_t b_lrow = (uint32_t)(lane & 7);
    const uint32_t b_lcol = (uint32_t)(((lane >> 3) & 1) << 3);

#pragma unroll
    for (int ks = 0; ks < 5; ks++) {
        const uint32_t kc = ks * 16;
        uint32_t Ah[4][4], Al[4][4], Bh[4][2], Bl[4][2];
#pragma unroll
        for (int mi = 0; mi < 4; mi++) {
            uint32_t off = ((m_blk + mi*16 + a_lrow)*AT_STRIDE + kc + a_lcol)*2;
            ldmat4(Ah[mi], smb + SM_AH + off);
            ldmat4(Al[mi], smb + SM_AL + off);
        }
#pragma unroll
        for (int ni = 0; ni < 4; ni++) {
            uint32_t off = ((n_blk + ni*8 + b_lrow)*AT_STRIDE + kc + b_lcol)*2;
            ldmat2(Bh[ni], smb + SM_BH + off);
            ldmat2(Bl[ni], smb + SM_BL + off);
        }
#pragma unroll
        for (int mi = 0; mi < 4; mi++)
#pragma unroll
            for (int ni = 0; ni < 4; ni++) {
                mma16816(acc[mi][ni], Ah[mi], Bh[ni]);
                mma16816(acc[mi][ni], Ah[mi], Bl[ni]);
                mma16816(acc[mi][ni], Al[mi], Bh[ni]);
            }
    }
    __syncthreads();

    const int gid = lane >> 2, tig = lane & 3;
    const float* sQ2 = (const float*)(smem + SM_Q2);
    const float* sK2 = (const float*)(smem + SM_K2);
#pragma unroll
    for (int mi = 0; mi < 4; mi++) {
        int r0 = m_blk + mi*16 + gid;
        int r1 = r0 + 8;
        float q20 = sQ2[r0], q21 = sQ2[r1];
#pragma unroll
        for (int ni = 0; ni < 4; ni++) {
            int c0 = n_blk + ni*8 + tig*2;
            float k20 = sK2[c0], k21 = sK2[c0 + 1];
            float2 lo, hi;
            lo.x = TEMP_*(2.f*acc[mi][ni][0] - q20 - k20);
            lo.y = TEMP_*(2.f*acc[mi][ni][1] - q20 - k21);
            hi.x = TEMP_*(2.f*acc[mi][ni][2] - q21 - k20);
            hi.y = TEMP_*(2.f*acc[mi][ni][3] - q21 - k21);
            *(float2*)(smem + SM_OUT + (r0*OUT_STRIDE + c0)*4) = lo;
            *(float2*)(smem + SM_OUT + (r1*OUT_STRIDE + c0)*4) = hi;
        }
    }
    __syncthreads();
#pragma unroll 4
    for (int it = 0; it < 16; it++) {
        int row = it*8 + (tid >> 5);
        float4 v = *(const float4*)(smem + SM_OUT + (row*OUT_STRIDE + lane*4)*4);
        *(float4*)&outp[((size_t)b*T2_ + t2_0 + row)*T1_ + t1_0 + lane*4] = v;
    }
}

// ====== conv: TT=256, 512 thr, pre-split W, 3-buffer cp.async ring ==========
template<int KSZ, int CIN>
struct CC4 {
    static constexpr int CB  = (CIN == 80) ? 80 : 64;
    static constexpr int NCB = CIN / CB;
    static constexpr int CVS = CB + 8;
    static constexpr int XR  = 256 + KSZ - 1;
    static constexpr int NKS = CB / 16;
    static constexpr int NJ  = NCB * KSZ;
    static constexpr int XHALF = XR * CVS * 2;
    static constexpr int WTAP  = 2 * HCH * CVS * 2;
    static constexpr int O_XH = 0;
    static constexpr int O_XL = XHALF;
    static constexpr int O_W  = 2*XHALF;
    static constexpr int O_BIAS = O_W + 3*WTAP;
    static constexpr int SMEM = O_BIAS + 512;
};
#define CV_TSTR 264

template<int KSZ, int PAD, int TLEN, int CIN, bool XPACKED, bool WF32>
__global__ void __launch_bounds__(512) conv_mma4(
        const void* __restrict__ xin, const __nv_bfloat16* __restrict__ wbf,
        const float* __restrict__ bias, float* __restrict__ yf,
        uint32_t* __restrict__ ypk)
{
    using C = CC4<KSZ, CIN>;
    extern __shared__ char smem[];
    const uint32_t smb = smem_u32(smem);
    const int tid  = threadIdx.x;
    const int wid  = tid >> 5;
    const int lane = tid & 31;
    const int t0   = blockIdx.x * 256;
    const int b    = blockIdx.y;

    if (tid < HCH) *(float*)(smem + C::O_BIAS + tid*4) = bias[tid];

    {   // prime tap 0 -> ring slot 0
        constexpr int CNT = C::WTAP / 16;
        for (int i = tid; i < CNT; i += 512)
            cp_async16(smb + C::O_W + i*16, (const char*)wbf + i*16);
        asm volatile("cp.async.commit_group;");
    }

    const int m_blk = (wid >> 1) * 32;
    const int n_blk = (wid & 1) * 40;

    float acc[2][5][4];
#pragma unroll
    for (int mi = 0; mi < 2; mi++)
#pragma unroll
        for (int ni = 0; ni < 5; ni++)
#pragma unroll
            for (int q = 0; q < 4; q++) acc[mi][ni][q] = 0.f;

    const uint32_t a_lrow = (uint32_t)(lane & 15);
    const uint32_t a_lcol = (uint32_t)((lane >> 4) << 3);
    const uint32_t b_lrow = (uint32_t)(lane & 7);
    const uint32_t b_lcol = (uint32_t)(((lane >> 3) & 1) << 3);

#pragma unroll 1
    for (int j = 0; j < C::NJ; j++) {
        const int cb = j / KSZ, k = j - cb*KSZ;
        if (k == 0) {
            if (j > 0) __syncthreads();   // X readers of prev cb done
            for (int idx = tid; idx < C::CB*C::XR; idx += 512) {
                int c = idx / C::XR, r = idx - c*C::XR;
                int t = t0 + r - PAD;
                bool inr = ((unsigned)t < (unsigned)TLEN);
                if (XPACKED) {
                    const uint32_t* xp = (const uint32_t*)xin;
                    uint32_t w = inr ? xp[((size_t)b*CIN + cb*C::CB + c)*TLEN + t] : 0u;
                    *(uint16_t*)(smem + C::O_XH + (r*C::CVS + c)*2) = (uint16_t)(w & 0xffffu);
                    *(uint16_t*)(smem + C::O_XL + (r*C::CVS + c)*2) = (uint16_t)(w >> 16);
                } else {
                    const float* xf = (const float*)xin;
                    float v = inr ? xf[((size_t)b*CIN + cb*C::CB + c)*TLEN + t] : 0.f;
                    __nv_bfloat16 h, l;
                    bf16split(v, h, l);
                    *(__nv_bfloat16*)(smem + C::O_XH + (r*C::CVS + c)*2) = h;
                    *(__nv_bfloat16*)(smem + C::O_XL + (r*C::CVS + c)*2) = l;
                }
            }
        }
        if (j + 1 < C::NJ) {   // prefetch next tap into ring slot (j+1)%3
            constexpr int CNT = C::WTAP / 16;
            uint32_t dst = smb + C::O_W + ((j+1) % 3) * C::WTAP;
            const char* src = (const char*)wbf + (size_t)(j+1)*C::WTAP;
            for (int i = tid; i < CNT; i += 512)
                cp_async16(dst + i*16, src + i*16);
            asm volatile("cp.async.commit_group;");
            asm volatile("cp.async.wait_group 1;");
        } else {
            asm volatile("cp.async.wait_group 0;");
        }
        __syncthreads();   // W slot j%3 + X visible to all

        const uint32_t wb = smb + C::O_W + (j % 3) * C::WTAP;
#pragma unroll
        for (int ks = 0; ks < C::NKS; ks++) {
            const uint32_t kc = ks * 16;
            uint32_t Ah[2][4], Al[2][4], Bh[5][2], Bl[5][2];
#pragma unroll
            for (int mi = 0; mi < 2; mi++) {
                uint32_t off = ((uint32_t)(m_blk + mi*16 + k + a_lrow)*C::CVS + kc + a_lcol)*2;
                ldmat4(Ah[mi], smb + C::O_XH + off);
                ldmat4(Al[mi], smb + C::O_XL + off);
            }
#pragma unroll
            for (int ni = 0; ni < 5; ni++) {
                uint32_t off = ((uint32_t)(n_blk + ni*8 + b_lrow)*C::CVS + kc + b_lcol)*2;
                ldmat2(Bh[ni], wb + off);
                ldmat2(Bl[ni], wb + HCH*C::CVS*2 + off);
            }
#pragma unroll
            for (int mi = 0; mi < 2; mi++)
#pragma unroll
                for (int ni = 0; ni < 5; ni++) {
                    mma16816(acc[mi][ni], Ah[mi], Bh[ni]);
                    mma16816(acc[mi][ni], Ah[mi], Bl[ni]);
                    mma16816(acc[mi][ni], Al[mi], Bh[ni]);
                }
        }
    }
    __syncthreads();   // done with X/W smem; bounce tile reuses it

    const int gid = lane >> 2, tig = lane & 3;
    const float* sB = (const float*)(smem + C::O_BIAS);
#pragma unroll
    for (int mi = 0; mi < 2; mi++) {
        int r0 = m_blk + mi*16 + gid;
        int r1 = r0 + 8;
#pragma unroll
        for (int ni = 0; ni < 5; ni++) {
            int c0 = n_blk + ni*8 + tig*2;
            float b0 = sB[c0], b1 = sB[c0+1];
            float v;
            v = acc[mi][ni][0] + b0; v = v >= 0.f ? v : SLOPE_*v;
            *(float*)(smem + (c0*CV_TSTR + r0)*4) = v;
            v = acc[mi][ni][1] + b1; v = v >= 0.f ? v : SLOPE_*v;
            *(float*)(smem + ((c0+1)*CV_TSTR + r0)*4) = v;
            v = acc[mi][ni][2] + b0; v = v >= 0.f ? v : SLOPE_*v;
            *(float*)(smem + (c0*CV_TSTR + r1)*4) = v;
            v = acc[mi][ni][3] + b1; v = v >= 0.f ? v : SLOPE_*v;
            *(float*)(smem + ((c0+1)*CV_TSTR + r1)*4) = v;
        }
    }
    __syncthreads();
    for (int idx = tid; idx < HCH*64; idx += 512) {
        int oc = idx >> 6, t4 = idx & 63;
        float4 v = *(const float4*)(smem + (oc*CV_TSTR + t4*4)*4);
        size_t o = ((size_t)b*HCH + oc)*TLEN + t0 + t4*4;
        if (WF32) *(float4*)&yf[o] = v;
        uint4 pk;
        pk.x = packhl(v.x); pk.y = packhl(v.y);
        pk.z = packhl(v.z); pk.w = packhl(v.w);
        *(uint4*)&ypk[o] = pk;
    }
}

// ---------------------------------------------------------------------------
__global__ void __launch_bounds__(256) transpose_logprior(
        const float* __restrict__ prior, float* __restrict__ lpT)
{
    __shared__ float tile[32][33];
    const int b = blockIdx.z;
    const int t1_0 = blockIdx.x * 32, t2_0 = blockIdx.y * 32;
    const int tx = threadIdx.x, ty = threadIdx.y;
#pragma unroll
    for (int i = 0; i < 4; i++)
        tile[ty + 8*i][tx] = prior[((size_t)b*T1_ + t1_0 + ty + 8*i)*T2_ + t2_0 + tx];
    __syncthreads();
#pragma unroll
    for (int i = 0; i < 4; i++)
        lpT[((size_t)b*T2_ + t2_0 + ty + 8*i)*T1_ + t1_0 + tx] =
            logf(tile[tx][ty + 8*i] + 1e-8f);
}

template<int C, int T>
__global__ void __launch_bounds__(256) sumsq_kernel(
        const float* __restrict__ x, float* __restrict__ out)
{
    int idx = blockIdx.x * 256 + threadIdx.x;
    int b = idx / T, t = idx - b*T;
    float s = 0.f;
#pragma unroll 8
    for (int c = 0; c < C; c++) {
        float v = x[((size_t)b*C + c)*T + t];
        s = fmaf(v, v, s);
    }
    out[idx] = s;
}

__device__ __forceinline__ float blkMax(float v, float* sh) {
#pragma unroll
    for (int o = 16; o; o >>= 1) v = fmaxf(v, __shfl_xor_sync(0xffffffffu, v, o));
    if ((threadIdx.x & 31) == 0) sh[threadIdx.x >> 5] = v;
    __syncthreads();
    float r = sh[0];
#pragma unroll
    for (int i = 1; i < 8; i++) r = fmaxf(r, sh[i]);
    __syncthreads();
    return r;
}
__device__ __forceinline__ float blkSum(float v, float* sh) {
#pragma unroll
    for (int o = 16; o; o >>= 1) v += __shfl_xor_sync(0xffffffffu, v, o);
    if ((threadIdx.x & 31) == 0) sh[threadIdx.x >> 5] = v;
    __syncthreads();
    float r = sh[0];
#pragma unroll
    for (int i = 1; i < 8; i++) r += sh[i];
    __syncthreads();
    return r;
}

__global__ void __launch_bounds__(256) rowsoft_kernel(
        float* __restrict__ lp, float* __restrict__ lpT,
        float* __restrict__ soft)
{
    __shared__ float sh[8];
    const size_t off = (size_t)blockIdx.x * T1_;
    const int tid = threadIdx.x;
    float v0 = lp[off + tid], v1 = lp[off + 256 + tid];
    float m  = blkMax(fmaxf(v0, v1), sh);
    float s  = blkSum(__expf(v0 - m) + __expf(v1 - m), sh);
    float lse = m + __logf(s);
    float a0 = v0 - lse + lpT[off + tid];
    float a1 = v1 - lse + lpT[off + 256 + tid];
    float m2 = blkMax(fmaxf(a0, a1), sh);
    float p0 = expf(a0 - m2), p1 = expf(a1 - m2);
    float s2 = blkSum(p0 + p1, sh);
    float inv = 1.0f / s2;
    float ls2 = logf(s2);
    lp[off + tid] = a0;                lp[off + 256 + tid] = a1;
    soft[off + tid] = p0 * inv;        soft[off + 256 + tid] = p1 * inv;
    lpT[off + tid] = a0 - m2 - ls2;    lpT[off + 256 + tid] = a1 - m2 - ls2;
}

__global__ void zero_kernel(float4* __restrict__ p) {
    size_t i = (size_t)blockIdx.x * blockDim.x + threadIdx.x;
    p[i] = make_float4(0.f, 0.f, 0.f, 0.f);
}

#define MAS_RING 8
#define MAS_SMEM (T2_*32*2 + T1_*4)

__global__ void __launch_bounds__(32) mas_kernel(
        const float* __restrict__ la, const int* __restrict__ enc_len,
        const int* __restrict__ dec_len, float* __restrict__ hard,
        float* __restrict__ dur)
{
    extern __shared__ unsigned short sBits[];
    int* durS = (int*)&sBits[T2_*32];
    const int b = blockIdx.x;
    const int lane = threadIdx.x;
    const int el = enc_len[b];
    const int dl = dec_len[b];
    const float* rowbase = la + (size_t)b*T2_*T1_ + lane*16;

    unsigned validbits = 0u;
    float logp[16];
#pragma unroll
    for (int k = 0; k < 16; k++) {
        logp[k] = (lane == 0 && k == 0) ? 0.f : NEGV;
        if (lane*16 + k < el) validbits |= (1u << k);
    }
    float4 ring[MAS_RING][4];
#pragma unroll
    for (int p = 0; p < MAS_RING; p++)
#pragma unroll
        for (int q = 0; q < 4; q++)
            ring[p][q] = *(const float4*)(rowbase + (size_t)p*T1_ + q*4);

    for (int t2b = 0; t2b < T2_; t2b += MAS_RING) {
#pragma unroll
        for (int u = 0; u < MAS_RING; u++) {
            const int t2 = t2b + u;
            float rv[16];
            rv[0]=ring[u][0].x;  rv[1]=ring[u][0].y;  rv[2]=ring[u][0].z;  rv[3]=ring[u][0].w;
            rv[4]=ring[u][1].x;  rv[5]=ring[u][1].y;  rv[6]=ring[u][1].z;  rv[7]=ring[u][1].w;
            rv[8]=ring[u][2].x;  rv[9]=ring[u][2].y;  rv[10]=ring[u][2].z; rv[11]=ring[u][2].w;
            rv[12]=ring[u][3].x; rv[13]=ring[u][3].y; rv[14]=ring[u][3].z; rv[15]=ring[u][3].w;
            const int tn = t2 + MAS_RING;
            if (tn < T2_) {
#pragma unroll
                for (int q = 0; q < 4; q++)
                    ring[u][q] = *(const float4*)(rowbase + (size_t)tn*T1_ + q*4);
            }
#pragma unroll
            for (int k = 0; k < 16; k++)
                rv[k] = ((validbits >> k) & 1u) ? rv[k] : NEGV;
            if (t2 == 0) {
#pragma unroll
                for (int k = 0; k < 16; k++)
                    if (lane > 0 || k > 0) rv[k] = NEGV;
            }
            float last = __shfl_up_sync(0xffffffffu, logp[15], 1);
            unsigned bits = 0u;
#pragma unroll
            for (int k = 15; k >= 0; k--) {
                float sh = (k == 0) ? last : logp[k-1];
                bool t1pos = (k > 0) || (lane > 0);
                bool take = t1pos && (sh >= logp[k]);
                float base = take ? sh : logp[k];
                if (take) bits |= (1u << k);
                logp[k] = rv[k] + base;
            }
            sBits[t2*32 + lane] = (unsigned short)bits;
        }
    }
    __syncwarp();
    for (int i = lane; i < T1_; i += 32) durS[i] = 0;
    __syncwarp();
    if (lane == 0) {
        int curr = el - 1;
        for (int i = T2_-1; i >= 0; --i) {
            if (i < dl) {
                hard[((size_t)b*T2_ + i)*T1_ + curr] = 1.0f;
                durS[curr]++;
                unsigned bits = sBits[i*32 + (curr >> 4)];
                curr -= (int)((bits >> (curr & 15)) & 1u);
            }
        }
    }
    __syncwarp();
    for (int i = lane; i < T1_; i += 32) dur[(size_t)b*T1_ + i] = (float)durS[i];
}

extern "C" void kernel_launch(void* const* d_in, const int* in_sizes, int n_in,
                              void* d_out, int out_size)
{
    const float* enc_in  = (const float*)d_in[0];
    const float* dec_in  = (const float*)d_in[1];
    const int*   enc_len = (const int*)d_in[2];
    const int*   dec_len = (const int*)d_in[3];
    const float* prior   = (const float*)d_in[5];
    const float* kw1 = (const float*)d_in[6];
    const float* kb1 = (const float*)d_in[7];
    const float* kw2 = (const float*)d_in[8];
    const float* kb2 = (const float*)d_in[9];
    const float* qw1 = (const float*)d_in[10];
    const float* qb1 = (const float*)d_in[11];
    const float* qw2 = (const float*)d_in[12];
    const float* qb2 = (const float*)d_in[13];
    const float* qw3 = (const float*)d_in[14];
    const float* qb3 = (const float*)d_in[15];

    float* outp = (float*)d_out;
    const size_t VOL = (size_t)B_*T2_*T1_;
    float* lp   = outp;
    float* soft = outp + VOL;
    float* hard = outp + 2*VOL;
    float* dur  = outp + 3*VOL;

    float *pK, *pQA, *pk2, *pq2, *plpT;
    uint32_t *ppkA, *ppkB, *ppkK1, *ppkK;
    __nv_bfloat16 *pWK1, *pWK2, *pWQ1, *pWQ2, *pWQ3;
    cudaGetSymbolAddress((void**)&pK,   g_K);
    cudaGetSymbolAddress((void**)&pQA,  g_QA);
    cudaGetSymbolAddress((void**)&pk2,  g_k2);
    cudaGetSymbolAddress((void**)&pq2,  g_q2);
    cudaGetSymbolAddress((void**)&plpT, g_lpT);
    cudaGetSymbolAddress((void**)&ppkA,  g_pkA);
    cudaGetSymbolAddress((void**)&ppkB,  g_pkB);
    cudaGetSymbolAddress((void**)&ppkK1, g_pkK1);
    cudaGetSymbolAddress((void**)&ppkK,  g_pkK);
    cudaGetSymbolAddress((void**)&pWK1, g_WK1);
    cudaGetSymbolAddress((void**)&pWK2, g_WK2);
    cudaGetSymbolAddress((void**)&pWQ1, g_WQ1);
    cudaGetSymbolAddress((void**)&pWQ2, g_WQ2);
    cudaGetSymbolAddress((void**)&pWQ3, g_WQ3);

    static int attrs_set = 0;
    if (!attrs_set) {
        cudaFuncSetAttribute(mas_kernel, cudaFuncAttributeMaxDynamicSharedMemorySize, MAS_SMEM);
        cudaFuncSetAttribute(attn_mma_kernel, cudaFuncAttributeMaxDynamicSharedMemorySize, ATTN_SMEM);
        cudaFuncSetAttribute(conv_mma4<7,3,T2_,HCH,false,false>,
            cudaFuncAttributeMaxDynamicSharedMemorySize, CC4<7,HCH>::SMEM);
        cudaFuncSetAttribute(conv_mma4<7,3,T2_,HCH,true,false>,
            cudaFuncAttributeMaxDynamicSharedMemorySize, CC4<7,HCH>::SMEM);
        cudaFuncSetAttribute(conv_mma4<7,3,T2_,HCH,true,true>,
            cudaFuncAttributeMaxDynamicSharedMemorySize, CC4<7,HCH>::SMEM);
        cudaFuncSetAttribute(conv_mma4<3,1,T1_,CENC,false,false>,
            cudaFuncAttributeMaxDynamicSharedMemorySize, CC4<3,CENC>::SMEM);
        cudaFuncSetAttribute(conv_mma4<3,1,T1_,HCH,true,true>,
            cudaFuncAttributeMaxDynamicSharedMemorySize, CC4<3,HCH>::SMEM);
        attrs_set = 1;
    }

    prep_all<<<1080, 256>>>(kw1, kw2, qw1, qw2, qw3, pWK1, pWK2, pWQ1, pWQ2, pWQ3);

    transpose_logprior<<<dim3(T1_/32, T2_/32, B_), dim3(32, 8)>>>(prior, plpT);

    conv_mma4<3,1,T1_,CENC,false,false><<<dim3(T1_/256, B_), 512, CC4<3,CENC>::SMEM>>>(
        enc_in, pWK1, kb1, nullptr, ppkK1);
    conv_mma4<3,1,T1_,HCH,true,true><<<dim3(T1_/256, B_), 512, CC4<3,HCH>::SMEM>>>(
        ppkK1, pWK2, kb2, pK, ppkK);
    conv_mma4<7,3,T2_,HCH,false,false><<<dim3(T2_/256, B_), 512, CC4<7,HCH>::SMEM>>>(
        dec_in, pWQ1, qb1, nullptr, ppkA);
    conv_mma4<7,3,T2_,HCH,true,false><<<dim3(T2_/256, B_), 512, CC4<7,HCH>::SMEM>>>(
        ppkA, pWQ2, qb2, nullptr, ppkB);
    conv_mma4<7,3,T2_,HCH,true,true><<<dim3(T2_/256, B_), 512, CC4<7,HCH>::SMEM>>>(
        ppkB, pWQ3, qb3, pQA, ppkA);

    sumsq_kernel<HCH, T1_><<<B_*T1_/256, 256>>>(pK,  pk2);
    sumsq_kernel<HCH, T2_><<<B_*T2_/256, 256>>>(pQA, pq2);

    attn_mma_kernel<<<dim3(T2_/128, T1_/128, B_), 256, ATTN_SMEM>>>(ppkA, ppkK, pq2, pk2, lp);
    rowsoft_kernel<<<B_*T2_, 256>>>(lp, plpT, soft);

    zero_kernel<<<(unsigned)(VOL/4/256), 256>>>((float4*)hard);

    mas_kernel<<<B_, 32, MAS_SMEM>>>(plpT, enc_len, dec_len, hard, dur);
}